// round 14
// baseline (speedup 1.0000x reference)
#include <cuda_runtime.h>
#include <cuda_fp16.h>
#include <cstdint>

// ============================ problem sizes ============================
#define BATCH   8192
#define INDIM   1024
#define OUTDIM  1024
#define DEG1    9
#define KD2     (INDIM * 8)         // 8192 GEMM K (d=1..8; d=0 folded into bias)
#define TM      64                  // tall-N tiles: halve A-producer redundancy
#define TN      128
#define KC      64                  // 8 inputs x 8 degrees per stage
#define NITER   (KD2 / KC)          // 128
#define NTH     128                 // 4 warps, warp tile 32x64

#define ASTW    36                  // row stride in 32-bit words
#define BSTW    36
#define ROWB    144                 // row stride in bytes
#define A_WORDS (TM * ASTW)         // 2304 words = 9216 B per stage
#define B_WORDS (TN * BSTW)         // 4608 words = 18432 B per slot
#define A_BYTES (A_WORDS * 4)
#define B_BYTES (B_WORDS * 4)
#define MBW     16                  // 64 B header for 6 mbarriers
#define SMEM_BYTES ((MBW + 2 * A_WORDS + 3 * B_WORDS) * 4)   // 73792 -> 3 CTAs/SM

#define CSCALE   64.0f
#define CINV     (1.0f / 64.0f)

// __device__ scratch (static: allocation-guard safe)
__device__ __half g_Bt[(size_t)OUTDIM * KD2];   // Bt[o][i*8+d-1] * 64, fp16
__device__ float  g_t[(size_t)BATCH * INDIM];   // clip(tanh(x))
__device__ float  g_bias[OUTDIM];               // sum_i C[i][o][0]

// ============================ helpers ==================================
__device__ __forceinline__ void cp_async16(uint32_t smem_dst, const void* gsrc) {
    asm volatile("cp.async.cg.shared.global [%0], [%1], 16;"
                 :: "r"(smem_dst), "l"(gsrc) : "memory");
}
__device__ __forceinline__ uint32_t smem_u32(const void* p) {
    uint32_t a;
    asm("{ .reg .u64 t; cvta.to.shared.u64 t, %1; cvt.u32.u64 %0, t; }" : "=r"(a) : "l"(p));
    return a;
}
#define MB_INIT(addr, cnt) \
    asm volatile("mbarrier.init.shared.b64 [%0], %1;" :: "r"(addr), "r"(cnt) : "memory")
#define MB_ARRIVE(addr) \
    asm volatile("{ .reg .b64 t; mbarrier.arrive.shared.b64 t, [%0]; }" :: "r"(addr) : "memory")
#define CP_MB_ARRIVE(addr) \
    asm volatile("cp.async.mbarrier.arrive.noinc.shared.b64 [%0];" :: "r"(addr) : "memory")
#define MB_WAIT(addr, parity) do {                                                       \
    uint32_t _mbar = (uint32_t)(addr);                                                   \
    uint32_t _par  = (uint32_t)(parity);                                                 \
    uint32_t _done;                                                                      \
    asm volatile("{\n\t.reg .pred p;\n\t"                                                \
        "mbarrier.try_wait.parity.acquire.cta.shared::cta.b64 p, [%1], %2;\n\t"          \
        "selp.b32 %0, 1, 0, p;\n\t}"                                                     \
        : "=r"(_done) : "r"(_mbar), "r"(_par) : "memory");                               \
    if (!_done) {                                                                        \
        asm volatile("{\n\t.reg .pred P1;\n\t"                                           \
            "WL_%=:\n\t"                                                                 \
            "mbarrier.try_wait.parity.acquire.cta.shared::cta.b64 P1, [%0], %1, 0x989680;\n\t" \
            "@P1 bra.uni WD_%=;\n\t"                                                     \
            "bra.uni WL_%=;\n\t"                                                         \
            "WD_%=:\n\t}"                                                                \
            :: "r"(_mbar), "r"(_par) : "memory");                                        \
    }                                                                                    \
} while (0)

// mma m16n8k16 row.col f32.f16.f16.f32 — NON-volatile (pure register op)
__device__ __forceinline__ void mma16(float* c, const uint32_t* a, uint32_t b0, uint32_t b1) {
    asm("mma.sync.aligned.m16n8k16.row.col.f32.f16.f16.f32 "
        "{%0,%1,%2,%3}, {%4,%5,%6,%7}, {%8,%9}, {%0,%1,%2,%3};"
        : "+f"(c[0]), "+f"(c[1]), "+f"(c[2]), "+f"(c[3])
        : "r"(a[0]), "r"(a[1]), "r"(a[2]), "r"(a[3]), "r"(b0), "r"(b1));
}
__device__ __forceinline__ void ldm4(uint32_t* r, uint32_t addr) {
    asm volatile("ldmatrix.sync.aligned.m8n8.x4.shared.b16 {%0,%1,%2,%3}, [%4];"
                 : "=r"(r[0]), "=r"(r[1]), "=r"(r[2]), "=r"(r[3]) : "r"(addr));
}

// ============ prep 1: t = clip(tanh(x)); blocks 0-3 zero g_bias ========
__global__ __launch_bounds__(256)
void prep_t_kernel(const float* __restrict__ x) {
    if (blockIdx.x < 4) g_bias[blockIdx.x * 256 + threadIdx.x] = 0.0f;
    size_t i4 = (size_t)blockIdx.x * 256 + threadIdx.x;
    const float4* src = (const float4*)x;
    float4* dst = (float4*)g_t;
    float4 v = src[i4];
    float4 r;
    r.x = fminf(fmaxf(tanhf(v.x), -0.999f), 0.999f);
    r.y = fminf(fmaxf(tanhf(v.y), -0.999f), 0.999f);
    r.z = fminf(fmaxf(tanhf(v.z), -0.999f), 0.999f);
    r.w = fminf(fmaxf(tanhf(v.w), -0.999f), 0.999f);
    dst[i4] = r;
}

// ==== prep 2: C[i,o,d>=1]*64 -> Bt[o, i*8+d-1]; d=0 -> atomic bias =====
__global__ __launch_bounds__(256)
void prep_Bt_kernel(const float* __restrict__ C) {
    int idx = blockIdx.x * 256 + threadIdx.x;   // over INDIM*OUTDIM
    int i = idx >> 10;
    int o = idx & 1023;
    const float* src = C + (size_t)i * (OUTDIM * DEG1) + (size_t)o * DEG1;
    __half* dst = g_Bt + (size_t)o * KD2 + (size_t)i * 8;
#pragma unroll
    for (int d = 1; d < DEG1; d++) dst[d - 1] = __float2half_rn(src[d] * CSCALE);
    atomicAdd(&g_bias[o], src[0]);              // T_0 == 1 contribution
}

// ============================ main GEMM ================================
__global__ __launch_bounds__(NTH, 3)
void cheby_gemm_kernel(float* __restrict__ out) {
    extern __shared__ uint32_t sm[];
    uint32_t* const Abuf = sm + MBW;                 // 2 stages (64 rows each)
    uint32_t* const Bbuf = sm + MBW + 2 * A_WORDS;   // 3 slots (128 rows each)
    const uint32_t mb = smem_u32(sm);                // full[s]=mb+16s, empty[s]=mb+16s+8

    const int tid  = threadIdx.x;
    const int wid  = tid >> 5;
    const int lane = tid & 31;
    const int gid  = lane >> 2;
    const int tg   = lane & 3;
    const int warp_m = wid & 1;     // 2 warps along M (32 rows each)
    const int warp_n = wid >> 1;    // 2 warps along N (64 cols each)
    const int m0 = blockIdx.x * TM;
    const int n0 = blockIdx.y * TN;

    if (tid == 0) {
#pragma unroll
        for (int s2 = 0; s2 < 3; s2++) {
            MB_INIT(mb + s2 * 16, NTH);       // full (B cp.async complete)
            MB_INIT(mb + s2 * 16 + 8, NTH);   // empty
        }
    }
    __syncthreads();   // one-time init fence

    float acc[2][8][4];
#pragma unroll
    for (int mf = 0; mf < 2; mf++)
#pragma unroll
        for (int nf = 0; nf < 8; nf++)
#pragma unroll
            for (int q = 0; q < 4; q++) acc[mf][nf][q] = 0.0f;

    // B copier: thread = row (128 rows x 32 words, 8 x cp16 each)
    const __half* browsrc = g_Bt + (size_t)(n0 + tid) * KD2;
    const uint32_t bdst_base = smem_u32(Bbuf) + (uint32_t)(tid * BSTW) * 4u;

    // ldmatrix per-lane base addresses
    const uint32_t a_ldm_base = smem_u32(Abuf)
        + (uint32_t)(warp_m * 32 + (lane & 7) + ((lane >> 3) & 1) * 8) * ROWB
        + (uint32_t)((lane >> 4) * 16);
    const uint32_t b_ldm_base = smem_u32(Bbuf)
        + (uint32_t)(warp_n * 64 + (lane & 7) + (lane >> 4) * 8) * ROWB
        + (uint32_t)(((lane >> 3) & 1) * 16);

    // ---- prologue: fill B slot0 (jj=0), slot1 (jj=1) ----
#pragma unroll
    for (int q = 0; q < 8; q++) cp_async16(bdst_base + q * 16, browsrc + q * 8);
    CP_MB_ARRIVE(mb + 0 * 16);
#pragma unroll
    for (int q = 0; q < 8; q++)
        cp_async16(bdst_base + B_BYTES + q * 16, browsrc + KC + q * 8);
    CP_MB_ARRIVE(mb + 1 * 16);

    // A producer: thread -> (row tid>>1, k-half tid&1): 4 inputs x deg 1..8
    const int prow = tid >> 1;
    const int phh  = tid & 1;
    const float4* tsrc = (const float4*)(g_t + (size_t)(m0 + prow) * INDIM);
    float4 t0 = tsrc[phh];                 // 4 inputs for jj=0
    {
        uint32_t* dst = Abuf + prow * ASTW + phh * 16;
#pragma unroll
        for (int e = 0; e < 4; e++) {
            float t = (&t0.x)[e];
            float t2 = t + t;
            float v[8];
            v[0] = t;
            float u0 = 1.0f, u1 = t;
#pragma unroll
            for (int d = 2; d <= 8; d++) {
                float u2 = fmaf(t2, u1, -u0);
                v[d - 1] = u2;
                u0 = u1; u1 = u2;
            }
            __half2 h0 = __floats2half2_rn(v[0], v[1]);
            __half2 h1 = __floats2half2_rn(v[2], v[3]);
            __half2 h2 = __floats2half2_rn(v[4], v[5]);
            __half2 h3 = __floats2half2_rn(v[6], v[7]);
            uint4 pk;
            pk.x = *(uint32_t*)&h0; pk.y = *(uint32_t*)&h1;
            pk.z = *(uint32_t*)&h2; pk.w = *(uint32_t*)&h3;
            *(uint4*)(dst + e * 4) = pk;
        }
    }
    float4 tn = tsrc[2 + phh];             // t for producing A[1]
    __syncthreads();                       // A[0] visible

    // ---- prologue: preload (jj=0, kc=0) fragments ----
    uint32_t afr[2][2][4], bfr[2][4][4];
    int pb = 0;
    MB_WAIT(mb + 0 * 16, 0);               // full[0], phase 0
#pragma unroll
    for (int mf = 0; mf < 2; mf++)
        ldm4(afr[0][mf], a_ldm_base + (uint32_t)(mf * 16 * ROWB));
#pragma unroll
    for (int p = 0; p < 4; p++)
        ldm4(bfr[0][p], b_ldm_base + (uint32_t)(p * 16 * ROWB));

    int bb = 0;        // jj % 3
    int q3 = 0;        // jj / 3

#pragma unroll 1
    for (int jj = 0; jj < NITER; jj++) {
        const int s = jj & 1;
        const uint32_t a_addr0 = a_ldm_base + (uint32_t)(s * A_BYTES);
        const uint32_t b_addr0 = b_ldm_base + (uint32_t)(bb * B_BYTES);

        // ---- kc = 0..2: prefetch kc+1, MMA kc (tensor engaged at once) ----
#pragma unroll
        for (int kc = 0; kc < 3; kc++) {
            const uint32_t kb = (kc + 1) * 32;
            const int nx = pb ^ 1;
#pragma unroll
            for (int mf = 0; mf < 2; mf++)
                ldm4(afr[nx][mf], a_addr0 + (uint32_t)(mf * 16 * ROWB) + kb);
#pragma unroll
            for (int p = 0; p < 4; p++)
                ldm4(bfr[nx][p], b_addr0 + (uint32_t)(p * 16 * ROWB) + kb);
#pragma unroll
            for (int p = 0; p < 4; p++) {
#pragma unroll
                for (int mf = 0; mf < 2; mf++) {
                    mma16(acc[mf][2 * p],     afr[pb][mf], bfr[pb][p][0], bfr[pb][p][1]);
                    mma16(acc[mf][2 * p + 1], afr[pb][mf], bfr[pb][p][2], bfr[pb][p][3]);
                }
            }
            pb ^= 1;
        }

        // ---- boundary work (kc3 MMAs held back to cover it) ----
        // produce A[jj+1] into stage s^1 (FMA pipe; hides under kc drain)
        if (jj + 1 < NITER) {
            uint32_t* dst = Abuf + (s ^ 1) * A_WORDS + prow * ASTW + phh * 16;
#pragma unroll
            for (int e = 0; e < 4; e++) {
                float t = (&tn.x)[e];
                float t2 = t + t;
                float v[8];
                v[0] = t;
                float u0 = 1.0f, u1 = t;
#pragma unroll
                for (int d = 2; d <= 8; d++) {
                    float u2 = fmaf(t2, u1, -u0);
                    v[d - 1] = u2;
                    u0 = u1; u1 = u2;
                }
                __half2 h0 = __floats2half2_rn(v[0], v[1]);
                __half2 h1 = __floats2half2_rn(v[2], v[3]);
                __half2 h2 = __floats2half2_rn(v[4], v[5]);
                __half2 h3 = __floats2half2_rn(v[6], v[7]);
                uint4 pk;
                pk.x = *(uint32_t*)&h0; pk.y = *(uint32_t*)&h1;
                pk.z = *(uint32_t*)&h2; pk.w = *(uint32_t*)&h3;
                *(uint4*)(dst + e * 4) = pk;
            }
            if (jj + 2 < NITER) tn = tsrc[(jj + 2) * 2 + phh];
        }

        // fill B[jj+2] into slot (bb+2)%3
        if (jj + 2 < NITER) {
            int bb2 = (bb >= 1) ? bb - 1 : 2;          // (bb+2)%3
            if (jj >= 1) {
                int pe = ((bb == 0) ? (q3 - 1) : q3) & 1;  // ((jj-1)/3)&1
                MB_WAIT(mb + bb2 * 16 + 8, pe);
            }
            const __half* src = browsrc + (jj + 2) * KC;
            uint32_t dst = bdst_base + (uint32_t)(bb2 * B_BYTES);
#pragma unroll
            for (int q = 0; q < 8; q++) cp_async16(dst + q * 16, src + q * 8);
            CP_MB_ARRIVE(mb + bb2 * 16);
        }

        // A[jj+1] visible; all A[s]/B[bb] ldm reads complete
        __syncthreads();
        MB_ARRIVE(mb + bb * 16 + 8);       // release B slot jj

        const int bbn = (bb == 2) ? 0 : bb + 1;
        const int q3n = (bb == 2) ? q3 + 1 : q3;

        // cross-jj prefetch: (jj+1, kc0) fragments before kc3 MMAs
        if (jj + 1 < NITER) {
            MB_WAIT(mb + bbn * 16, q3n & 1);
            const uint32_t a_n = a_ldm_base + (uint32_t)((s ^ 1) * A_BYTES);
            const uint32_t b_n = b_ldm_base + (uint32_t)(bbn * B_BYTES);
            const int nx = pb ^ 1;
#pragma unroll
            for (int mf = 0; mf < 2; mf++)
                ldm4(afr[nx][mf], a_n + (uint32_t)(mf * 16 * ROWB));
#pragma unroll
            for (int p = 0; p < 4; p++)
                ldm4(bfr[nx][p], b_n + (uint32_t)(p * 16 * ROWB));
        }

        // ---- kc3 MMAs: cover the boundary latency ----
#pragma unroll
        for (int p = 0; p < 4; p++) {
#pragma unroll
            for (int mf = 0; mf < 2; mf++) {
                mma16(acc[mf][2 * p],     afr[pb][mf], bfr[pb][p][0], bfr[pb][p][1]);
                mma16(acc[mf][2 * p + 1], afr[pb][mf], bfr[pb][p][2], bfr[pb][p][3]);
            }
        }
        pb ^= 1;

        bb = bbn; q3 = q3n;
    }

    // ---- epilogue: unscale, add T0 bias, write D ----
#pragma unroll
    for (int nf = 0; nf < 8; nf++) {
        int col = n0 + warp_n * 64 + nf * 8 + tg * 2;
        float2 bv = *(const float2*)&g_bias[col];
#pragma unroll
        for (int mf = 0; mf < 2; mf++) {
            int row = m0 + warp_m * 32 + mf * 16 + gid;
            float2* p0 = (float2*)(out + (size_t)row * OUTDIM + col);
            float2* p1 = (float2*)(out + (size_t)(row + 8) * OUTDIM + col);
            *p0 = make_float2(fmaf(acc[mf][nf][0], CINV, bv.x),
                              fmaf(acc[mf][nf][1], CINV, bv.y));
            *p1 = make_float2(fmaf(acc[mf][nf][2], CINV, bv.x),
                              fmaf(acc[mf][nf][3], CINV, bv.y));
        }
    }
}

// ============================ host launch ==============================
extern "C" void kernel_launch(void* const* d_in, const int* in_sizes, int n_in,
                              void* d_out, int out_size) {
    const float* x;
    const float* C;
    if (in_sizes[0] == BATCH * INDIM) { x = (const float*)d_in[0]; C = (const float*)d_in[1]; }
    else                              { x = (const float*)d_in[1]; C = (const float*)d_in[0]; }
    float* out = (float*)d_out;

    prep_t_kernel<<<(BATCH * INDIM) / (256 * 4), 256>>>(x);
    prep_Bt_kernel<<<(INDIM * OUTDIM) / 256, 256>>>(C);

    static int smem_set = 0;
    if (!smem_set) {
        cudaFuncSetAttribute(cheby_gemm_kernel,
                             cudaFuncAttributeMaxDynamicSharedMemorySize, SMEM_BYTES);
        smem_set = 1;
    }
    dim3 grid(BATCH / TM, OUTDIM / TN, 1);   // 128 x 8 = 1024 CTAs, 3/SM
    cheby_gemm_kernel<<<grid, NTH, SMEM_BYTES>>>(out);
}

// round 15
// speedup vs baseline: 1.4450x; 1.4450x over previous
#include <cuda_runtime.h>
#include <cuda_fp16.h>
#include <cstdint>

// ============================ problem sizes ============================
#define BATCH   8192
#define INDIM   1024
#define OUTDIM  1024
#define DEG1    9
#define KD2     (INDIM * 8)         // 8192 GEMM K (d=1..8; d=0 folded into bias)
#define TM      128
#define TN      64                  // finer N-tiles: 1024 CTAs -> 1.2% imbalance
#define KC      64                  // 8 inputs x 8 degrees per stage
#define NITER   (KD2 / KC)          // 128
#define NTH     128                 // 4 warps, warp tile 64x32

#define ASTW    36                  // A row stride in 32-bit words
#define BSTW    36
#define ROWB    144                 // row stride in bytes
#define A_WORDS (TM * ASTW)         // 4608 words = 18432 B per stage
#define B_WORDS (TN * BSTW)         // 2304 words = 9216 B per slot
#define A_BYTES (A_WORDS * 4)
#define B_BYTES (B_WORDS * 4)
#define MBW     16                  // 64 B header for 6 mbarriers
#define SMEM_BYTES ((MBW + 2 * A_WORDS + 3 * B_WORDS) * 4)   // 64576 -> 3 CTAs/SM

#define CSCALE   64.0f
#define CINV     (1.0f / 64.0f)

// __device__ scratch (static: allocation-guard safe)
__device__ __half g_Bt[(size_t)OUTDIM * KD2];   // Bt[o][i*8+d-1] * 64, fp16
__device__ float  g_t[(size_t)BATCH * INDIM];   // clip(tanh(x))
__device__ float  g_bias[OUTDIM];               // sum_i C[i][o][0]

// ============================ helpers ==================================
__device__ __forceinline__ void cp_async16(uint32_t smem_dst, const void* gsrc) {
    asm volatile("cp.async.cg.shared.global [%0], [%1], 16;"
                 :: "r"(smem_dst), "l"(gsrc) : "memory");
}
__device__ __forceinline__ uint32_t smem_u32(const void* p) {
    uint32_t a;
    asm("{ .reg .u64 t; cvta.to.shared.u64 t, %1; cvt.u32.u64 %0, t; }" : "=r"(a) : "l"(p));
    return a;
}
#define MB_INIT(addr, cnt) \
    asm volatile("mbarrier.init.shared.b64 [%0], %1;" :: "r"(addr), "r"(cnt) : "memory")
#define MB_ARRIVE(addr) \
    asm volatile("{ .reg .b64 t; mbarrier.arrive.shared.b64 t, [%0]; }" :: "r"(addr) : "memory")
#define CP_MB_ARRIVE(addr) \
    asm volatile("cp.async.mbarrier.arrive.noinc.shared.b64 [%0];" :: "r"(addr) : "memory")
#define MB_WAIT(addr, parity) do {                                                       \
    uint32_t _mbar = (uint32_t)(addr);                                                   \
    uint32_t _par  = (uint32_t)(parity);                                                 \
    uint32_t _done;                                                                      \
    asm volatile("{\n\t.reg .pred p;\n\t"                                                \
        "mbarrier.try_wait.parity.acquire.cta.shared::cta.b64 p, [%1], %2;\n\t"          \
        "selp.b32 %0, 1, 0, p;\n\t}"                                                     \
        : "=r"(_done) : "r"(_mbar), "r"(_par) : "memory");                               \
    if (!_done) {                                                                        \
        asm volatile("{\n\t.reg .pred P1;\n\t"                                           \
            "WL_%=:\n\t"                                                                 \
            "mbarrier.try_wait.parity.acquire.cta.shared::cta.b64 P1, [%0], %1, 0x989680;\n\t" \
            "@P1 bra.uni WD_%=;\n\t"                                                     \
            "bra.uni WL_%=;\n\t"                                                         \
            "WD_%=:\n\t}"                                                                \
            :: "r"(_mbar), "r"(_par) : "memory");                                        \
    }                                                                                    \
} while (0)

// mma m16n8k16 row.col f32.f16.f16.f32 — NON-volatile (pure register op)
__device__ __forceinline__ void mma16(float* c, const uint32_t* a, uint32_t b0, uint32_t b1) {
    asm("mma.sync.aligned.m16n8k16.row.col.f32.f16.f16.f32 "
        "{%0,%1,%2,%3}, {%4,%5,%6,%7}, {%8,%9}, {%0,%1,%2,%3};"
        : "+f"(c[0]), "+f"(c[1]), "+f"(c[2]), "+f"(c[3])
        : "r"(a[0]), "r"(a[1]), "r"(a[2]), "r"(a[3]), "r"(b0), "r"(b1));
}
__device__ __forceinline__ void ldm4(uint32_t* r, uint32_t addr) {
    asm volatile("ldmatrix.sync.aligned.m8n8.x4.shared.b16 {%0,%1,%2,%3}, [%4];"
                 : "=r"(r[0]), "=r"(r[1]), "=r"(r[2]), "=r"(r[3]) : "r"(addr));
}

// ============ prep 1: t = clip(tanh(x)); blocks 0-3 zero g_bias ========
__global__ __launch_bounds__(256)
void prep_t_kernel(const float* __restrict__ x) {
    if (blockIdx.x < 4) g_bias[blockIdx.x * 256 + threadIdx.x] = 0.0f;
    size_t i4 = (size_t)blockIdx.x * 256 + threadIdx.x;
    const float4* src = (const float4*)x;
    float4* dst = (float4*)g_t;
    float4 v = src[i4];
    float4 r;
    r.x = fminf(fmaxf(tanhf(v.x), -0.999f), 0.999f);
    r.y = fminf(fmaxf(tanhf(v.y), -0.999f), 0.999f);
    r.z = fminf(fmaxf(tanhf(v.z), -0.999f), 0.999f);
    r.w = fminf(fmaxf(tanhf(v.w), -0.999f), 0.999f);
    dst[i4] = r;
}

// ==== prep 2: C[i,o,d>=1]*64 -> Bt[o, i*8+d-1]; d=0 -> atomic bias =====
// smem-transposed: reads coalesced over o, writes coalesced over i
// (each warp stores 512 B contiguous runs of g_Bt instead of 16 B x 16 KB
// scattered chunks). Tile: 32 i x 64 o per 256-thread block.
__global__ __launch_bounds__(256)
void prep_Bt_kernel(const float* __restrict__ C) {
    __shared__ uint4 sm4[64][33];               // [oo][ii], padded
    const int i0 = (blockIdx.x >> 4) * 32;      // 32 i-blocks
    const int o0 = (blockIdx.x & 15) * 64;      // 16 o-blocks
    const int tid = threadIdx.x;

    // read phase: 2048 (ii,oo) pairs, 8 per thread, coalesced over oo
#pragma unroll
    for (int k = 0; k < 8; k++) {
        int p  = tid + k * 256;
        int ii = p >> 6;
        int oo = p & 63;
        const float* src = C + (size_t)(i0 + ii) * (OUTDIM * DEG1)
                             + (size_t)(o0 + oo) * DEG1;
        float f0 = src[0];
        __half2 h0 = __floats2half2_rn(src[1] * CSCALE, src[2] * CSCALE);
        __half2 h1 = __floats2half2_rn(src[3] * CSCALE, src[4] * CSCALE);
        __half2 h2 = __floats2half2_rn(src[5] * CSCALE, src[6] * CSCALE);
        __half2 h3 = __floats2half2_rn(src[7] * CSCALE, src[8] * CSCALE);
        uint4 pk;
        pk.x = *(uint32_t*)&h0; pk.y = *(uint32_t*)&h1;
        pk.z = *(uint32_t*)&h2; pk.w = *(uint32_t*)&h3;
        sm4[oo][ii] = pk;
        atomicAdd(&g_bias[o0 + oo], f0);        // T_0 == 1 contribution
    }
    __syncthreads();

    // write phase: warp w handles oo = w*8..w*8+7; lane = ii -> 512 B runs
    const int w = tid >> 5;
    const int l = tid & 31;
#pragma unroll
    for (int r = 0; r < 8; r++) {
        int oo = w * 8 + r;
        uint4* dst = (uint4*)(g_Bt + (size_t)(o0 + oo) * KD2 + (size_t)i0 * 8);
        dst[l] = sm4[oo][l];
    }
}

// ============================ main GEMM ================================
__global__ __launch_bounds__(NTH, 3)
void cheby_gemm_kernel(float* __restrict__ out) {
    extern __shared__ uint32_t sm[];
    uint32_t* const Abuf = sm + MBW;                 // 2 stages
    uint32_t* const Bbuf = sm + MBW + 2 * A_WORDS;   // 3 slots
    const uint32_t mb = smem_u32(sm);                // full[s]=mb+16s, empty[s]=mb+16s+8

    const int tid  = threadIdx.x;
    const int wid  = tid >> 5;
    const int lane = tid & 31;
    const int gid  = lane >> 2;
    const int tg   = lane & 3;
    const int warp_m = wid & 1;     // 2 warps along M (64 rows each)
    const int warp_n = wid >> 1;    // 2 warps along N (32 cols each)
    const int m0 = blockIdx.x * TM;
    const int n0 = blockIdx.y * TN;

    if (tid == 0) {
#pragma unroll
        for (int s2 = 0; s2 < 3; s2++) {
            MB_INIT(mb + s2 * 16, NTH);       // full (B cp.async complete)
            MB_INIT(mb + s2 * 16 + 8, NTH);   // empty
        }
    }
    __syncthreads();   // one-time init fence

    float acc[4][4][4];
#pragma unroll
    for (int mf = 0; mf < 4; mf++)
#pragma unroll
        for (int nf = 0; nf < 4; nf++)
#pragma unroll
            for (int q = 0; q < 4; q++) acc[mf][nf][q] = 0.0f;

    // B copier: 128 threads, thread -> (row tid&63, half tid>>6), 4 cp16 each
    const int brow = tid & 63;
    const int bhalf = tid >> 6;
    const __half* browsrc = g_Bt + (size_t)(n0 + brow) * KD2 + bhalf * 32;
    const uint32_t bdst_base = smem_u32(Bbuf) + (uint32_t)(brow * BSTW + bhalf * 16) * 4u;

    // ldmatrix per-lane base addresses
    const uint32_t a_ldm_base = smem_u32(Abuf)
        + (uint32_t)(warp_m * 64 + (lane & 7) + ((lane >> 3) & 1) * 8) * ROWB
        + (uint32_t)((lane >> 4) * 16);
    const uint32_t b_ldm_base = smem_u32(Bbuf)
        + (uint32_t)(warp_n * 32 + (lane & 7) + (lane >> 4) * 8) * ROWB
        + (uint32_t)(((lane >> 3) & 1) * 16);

    // ---- prologue: fill B slot0 (jj=0), slot1 (jj=1) ----
#pragma unroll
    for (int q = 0; q < 4; q++) cp_async16(bdst_base + q * 16, browsrc + q * 8);
    CP_MB_ARRIVE(mb + 0 * 16);
#pragma unroll
    for (int q = 0; q < 4; q++)
        cp_async16(bdst_base + B_BYTES + q * 16, browsrc + KC + q * 8);
    CP_MB_ARRIVE(mb + 1 * 16);

    // A producer: thread = row tid, full 64-wide K row (8 inputs x deg 1..8)
    const float4* tsrc = (const float4*)(g_t + (size_t)(m0 + tid) * INDIM);
    float4 t0 = tsrc[0], t1 = tsrc[1];     // inputs 0..7 for jj=0
    {
        uint32_t* dst = Abuf + tid * ASTW;
#pragma unroll
        for (int e = 0; e < 8; e++) {
            float t = (e < 4) ? (&t0.x)[e] : (&t1.x)[e - 4];
            float t2 = t + t;
            float v[8];
            v[0] = t;
            float u0 = 1.0f, u1 = t;
#pragma unroll
            for (int d = 2; d <= 8; d++) {
                float u2 = fmaf(t2, u1, -u0);
                v[d - 1] = u2;
                u0 = u1; u1 = u2;
            }
            __half2 h0 = __floats2half2_rn(v[0], v[1]);
            __half2 h1 = __floats2half2_rn(v[2], v[3]);
            __half2 h2 = __floats2half2_rn(v[4], v[5]);
            __half2 h3 = __floats2half2_rn(v[6], v[7]);
            uint4 pk;
            pk.x = *(uint32_t*)&h0; pk.y = *(uint32_t*)&h1;
            pk.z = *(uint32_t*)&h2; pk.w = *(uint32_t*)&h3;
            *(uint4*)(dst + e * 4) = pk;
        }
    }
    t0 = tsrc[2]; t1 = tsrc[3];            // t for producing A[1]
    __syncthreads();                       // A[0] visible

    // ---- prologue: preload (jj=0, kc=0) fragments ----
    uint32_t afr[2][4][4], bfr[2][2][4];
    int pb = 0;
    MB_WAIT(mb + 0 * 16, 0);               // full[0], phase 0
#pragma unroll
    for (int mf = 0; mf < 4; mf++)
        ldm4(afr[0][mf], a_ldm_base + (uint32_t)(mf * 16 * ROWB));
#pragma unroll
    for (int p = 0; p < 2; p++)
        ldm4(bfr[0][p], b_ldm_base + (uint32_t)(p * 16 * ROWB));

    int bb = 0;        // jj % 3
    int q3 = 0;        // jj / 3

#pragma unroll 1
    for (int jj = 0; jj < NITER; jj++) {
        const int s = jj & 1;
        const uint32_t a_addr0 = a_ldm_base + (uint32_t)(s * A_BYTES);
        const uint32_t b_addr0 = b_ldm_base + (uint32_t)(bb * B_BYTES);

        // ---- kc = 0..2: prefetch kc+1, MMA kc (tensor engaged at once) ----
#pragma unroll
        for (int kc = 0; kc < 3; kc++) {
            const uint32_t kb = (kc + 1) * 32;
            const int nx = pb ^ 1;
#pragma unroll
            for (int mf = 0; mf < 4; mf++)
                ldm4(afr[nx][mf], a_addr0 + (uint32_t)(mf * 16 * ROWB) + kb);
#pragma unroll
            for (int p = 0; p < 2; p++)
                ldm4(bfr[nx][p], b_addr0 + (uint32_t)(p * 16 * ROWB) + kb);
#pragma unroll
            for (int p = 0; p < 2; p++) {
#pragma unroll
                for (int mf = 0; mf < 4; mf++) {
                    mma16(acc[mf][2 * p],     afr[pb][mf], bfr[pb][p][0], bfr[pb][p][1]);
                    mma16(acc[mf][2 * p + 1], afr[pb][mf], bfr[pb][p][2], bfr[pb][p][3]);
                }
            }
            pb ^= 1;
        }

        // ---- boundary work (kc3 MMAs held back to cover it) ----
        // produce A[jj+1] into stage s^1 (FMA pipe; hides under kc drain)
        if (jj + 1 < NITER) {
            uint32_t* dst = Abuf + (s ^ 1) * A_WORDS + tid * ASTW;
#pragma unroll
            for (int e = 0; e < 8; e++) {
                float t = (e < 4) ? (&t0.x)[e] : (&t1.x)[e - 4];
                float t2 = t + t;
                float v[8];
                v[0] = t;
                float u0 = 1.0f, u1 = t;
#pragma unroll
                for (int d = 2; d <= 8; d++) {
                    float u2 = fmaf(t2, u1, -u0);
                    v[d - 1] = u2;
                    u0 = u1; u1 = u2;
                }
                __half2 h0 = __floats2half2_rn(v[0], v[1]);
                __half2 h1 = __floats2half2_rn(v[2], v[3]);
                __half2 h2 = __floats2half2_rn(v[4], v[5]);
                __half2 h3 = __floats2half2_rn(v[6], v[7]);
                uint4 pk;
                pk.x = *(uint32_t*)&h0; pk.y = *(uint32_t*)&h1;
                pk.z = *(uint32_t*)&h2; pk.w = *(uint32_t*)&h3;
                *(uint4*)(dst + e * 4) = pk;
            }
            if (jj + 2 < NITER) {
                t0 = tsrc[(jj + 2) * 2];
                t1 = tsrc[(jj + 2) * 2 + 1];
            }
        }

        // fill B[jj+2] into slot (bb+2)%3
        if (jj + 2 < NITER) {
            int bb2 = (bb >= 1) ? bb - 1 : 2;          // (bb+2)%3
            if (jj >= 1) {
                int pe = ((bb == 0) ? (q3 - 1) : q3) & 1;  // ((jj-1)/3)&1
                MB_WAIT(mb + bb2 * 16 + 8, pe);
            }
            const __half* src = browsrc + (jj + 2) * KC;
            uint32_t dst = bdst_base + (uint32_t)(bb2 * B_BYTES);
#pragma unroll
            for (int q = 0; q < 4; q++) cp_async16(dst + q * 16, src + q * 8);
            CP_MB_ARRIVE(mb + bb2 * 16);
        }

        // A[jj+1] visible; all A[s]/B[bb] ldm reads complete
        __syncthreads();
        MB_ARRIVE(mb + bb * 16 + 8);       // release B slot jj

        const int bbn = (bb == 2) ? 0 : bb + 1;
        const int q3n = (bb == 2) ? q3 + 1 : q3;

        // cross-jj prefetch: (jj+1, kc0) fragments before kc3 MMAs
        if (jj + 1 < NITER) {
            MB_WAIT(mb + bbn * 16, q3n & 1);
            const uint32_t a_n = a_ldm_base + (uint32_t)((s ^ 1) * A_BYTES);
            const uint32_t b_n = b_ldm_base + (uint32_t)(bbn * B_BYTES);
            const int nx = pb ^ 1;
#pragma unroll
            for (int mf = 0; mf < 4; mf++)
                ldm4(afr[nx][mf], a_n + (uint32_t)(mf * 16 * ROWB));
#pragma unroll
            for (int p = 0; p < 2; p++)
                ldm4(bfr[nx][p], b_n + (uint32_t)(p * 16 * ROWB));
        }

        // ---- kc3 MMAs: cover the boundary latency ----
#pragma unroll
        for (int p = 0; p < 2; p++) {
#pragma unroll
            for (int mf = 0; mf < 4; mf++) {
                mma16(acc[mf][2 * p],     afr[pb][mf], bfr[pb][p][0], bfr[pb][p][1]);
                mma16(acc[mf][2 * p + 1], afr[pb][mf], bfr[pb][p][2], bfr[pb][p][3]);
            }
        }
        pb ^= 1;

        bb = bbn; q3 = q3n;
    }

    // ---- epilogue: unscale, add T0 bias, write D ----
#pragma unroll
    for (int nf = 0; nf < 4; nf++) {
        int col = n0 + warp_n * 32 + nf * 8 + tg * 2;
        float2 bv = *(const float2*)&g_bias[col];
#pragma unroll
        for (int mf = 0; mf < 4; mf++) {
            int row = m0 + warp_m * 64 + mf * 16 + gid;
            float2* p0 = (float2*)(out + (size_t)row * OUTDIM + col);
            float2* p1 = (float2*)(out + (size_t)(row + 8) * OUTDIM + col);
            *p0 = make_float2(fmaf(acc[mf][nf][0], CINV, bv.x),
                              fmaf(acc[mf][nf][1], CINV, bv.y));
            *p1 = make_float2(fmaf(acc[mf][nf][2], CINV, bv.x),
                              fmaf(acc[mf][nf][3], CINV, bv.y));
        }
    }
}

// ============================ host launch ==============================
extern "C" void kernel_launch(void* const* d_in, const int* in_sizes, int n_in,
                              void* d_out, int out_size) {
    const float* x;
    const float* C;
    if (in_sizes[0] == BATCH * INDIM) { x = (const float*)d_in[0]; C = (const float*)d_in[1]; }
    else                              { x = (const float*)d_in[1]; C = (const float*)d_in[0]; }
    float* out = (float*)d_out;

    prep_t_kernel<<<(BATCH * INDIM) / (256 * 4), 256>>>(x);
    prep_Bt_kernel<<<512, 256>>>(C);

    static int smem_set = 0;
    if (!smem_set) {
        cudaFuncSetAttribute(cheby_gemm_kernel,
                             cudaFuncAttributeMaxDynamicSharedMemorySize, SMEM_BYTES);
        smem_set = 1;
    }
    dim3 grid(BATCH / TM, OUTDIM / TN, 1);   // 64 x 16 = 1024 CTAs, 3/SM
    cheby_gemm_kernel<<<grid, NTH, SMEM_BYTES>>>(out);
}

// round 16
// speedup vs baseline: 1.4546x; 1.0066x over previous
#include <cuda_runtime.h>
#include <cuda_fp16.h>
#include <cstdint>

// ============================ problem sizes ============================
#define BATCH   8192
#define INDIM   1024
#define OUTDIM  1024
#define DEG1    9
#define KD2     (INDIM * 8)         // 8192 GEMM K (d=1..8; d=0 folded into bias)
#define TM      128
#define TN      64                  // finer N-tiles: 1024 CTAs -> 1.2% imbalance
#define KC      64                  // 8 inputs x 8 degrees per stage
#define NITER   (KD2 / KC)          // 128
#define NTH     128                 // 4 warps, warp tile 64x32

#define ASTW    36                  // A row stride in 32-bit words
#define BSTW    36
#define ROWB    144                 // row stride in bytes
#define A_WORDS (TM * ASTW)         // 4608 words = 18432 B per stage
#define B_WORDS (TN * BSTW)         // 2304 words = 9216 B per slot
#define A_BYTES (A_WORDS * 4)
#define B_BYTES (B_WORDS * 4)
#define MBW     16                  // 64 B header for 6 mbarriers
#define SMEM_BYTES ((MBW + 2 * A_WORDS + 3 * B_WORDS) * 4)   // 64576 -> 3 CTAs/SM

#define CSCALE   64.0f
#define CINV     (1.0f / 64.0f)

// __device__ scratch (static: allocation-guard safe)
__device__ __half g_Bt[(size_t)OUTDIM * KD2];   // Bt[o][i*8+d-1] * 64, fp16
__device__ float  g_t[(size_t)BATCH * INDIM];   // clip(tanh(x))
__device__ float  g_bias[OUTDIM];               // sum_i C[i][o][0]

// ============================ helpers ==================================
__device__ __forceinline__ void cp_async16(uint32_t smem_dst, const void* gsrc) {
    asm volatile("cp.async.cg.shared.global [%0], [%1], 16;"
                 :: "r"(smem_dst), "l"(gsrc) : "memory");
}
__device__ __forceinline__ uint32_t smem_u32(const void* p) {
    uint32_t a;
    asm("{ .reg .u64 t; cvta.to.shared.u64 t, %1; cvt.u32.u64 %0, t; }" : "=r"(a) : "l"(p));
    return a;
}
#define MB_INIT(addr, cnt) \
    asm volatile("mbarrier.init.shared.b64 [%0], %1;" :: "r"(addr), "r"(cnt) : "memory")
#define MB_ARRIVE(addr) \
    asm volatile("{ .reg .b64 t; mbarrier.arrive.shared.b64 t, [%0]; }" :: "r"(addr) : "memory")
#define CP_MB_ARRIVE(addr) \
    asm volatile("cp.async.mbarrier.arrive.noinc.shared.b64 [%0];" :: "r"(addr) : "memory")
#define MB_WAIT(addr, parity) do {                                                       \
    uint32_t _mbar = (uint32_t)(addr);                                                   \
    uint32_t _par  = (uint32_t)(parity);                                                 \
    uint32_t _done;                                                                      \
    asm volatile("{\n\t.reg .pred p;\n\t"                                                \
        "mbarrier.try_wait.parity.acquire.cta.shared::cta.b64 p, [%1], %2;\n\t"          \
        "selp.b32 %0, 1, 0, p;\n\t}"                                                     \
        : "=r"(_done) : "r"(_mbar), "r"(_par) : "memory");                               \
    if (!_done) {                                                                        \
        asm volatile("{\n\t.reg .pred P1;\n\t"                                           \
            "WL_%=:\n\t"                                                                 \
            "mbarrier.try_wait.parity.acquire.cta.shared::cta.b64 P1, [%0], %1, 0x989680;\n\t" \
            "@P1 bra.uni WD_%=;\n\t"                                                     \
            "bra.uni WL_%=;\n\t"                                                         \
            "WD_%=:\n\t}"                                                                \
            :: "r"(_mbar), "r"(_par) : "memory");                                        \
    }                                                                                    \
} while (0)

// mma m16n8k16 row.col f32.f16.f16.f32 — NON-volatile (pure register op)
__device__ __forceinline__ void mma16(float* c, const uint32_t* a, uint32_t b0, uint32_t b1) {
    asm("mma.sync.aligned.m16n8k16.row.col.f32.f16.f16.f32 "
        "{%0,%1,%2,%3}, {%4,%5,%6,%7}, {%8,%9}, {%0,%1,%2,%3};"
        : "+f"(c[0]), "+f"(c[1]), "+f"(c[2]), "+f"(c[3])
        : "r"(a[0]), "r"(a[1]), "r"(a[2]), "r"(a[3]), "r"(b0), "r"(b1));
}
__device__ __forceinline__ void ldm4(uint32_t* r, uint32_t addr) {
    asm volatile("ldmatrix.sync.aligned.m8n8.x4.shared.b16 {%0,%1,%2,%3}, [%4];"
                 : "=r"(r[0]), "=r"(r[1]), "=r"(r[2]), "=r"(r[3]) : "r"(addr));
}

// ============ prep 1: t = clip(tanh(x)); blocks 0-3 zero g_bias ========
__global__ __launch_bounds__(256)
void prep_t_kernel(const float* __restrict__ x) {
    if (blockIdx.x < 4) g_bias[blockIdx.x * 256 + threadIdx.x] = 0.0f;
    size_t i4 = (size_t)blockIdx.x * 256 + threadIdx.x;
    const float4* src = (const float4*)x;
    float4* dst = (float4*)g_t;
    float4 v = src[i4];
    float4 r;
    r.x = fminf(fmaxf(tanhf(v.x), -0.999f), 0.999f);
    r.y = fminf(fmaxf(tanhf(v.y), -0.999f), 0.999f);
    r.z = fminf(fmaxf(tanhf(v.z), -0.999f), 0.999f);
    r.w = fminf(fmaxf(tanhf(v.w), -0.999f), 0.999f);
    dst[i4] = r;
}

// ==== prep 2: C[i,o,d>=1]*64 -> Bt[o, i*8+d-1]; d=0 -> bias ============
// smem-transposed: reads coalesced over o, writes coalesced over i.
// Bias: oo = (tid + k*256) & 63 == tid & 63 is constant per thread, so the
// 8 k-iterations accumulate in a register -> ONE atomicAdd per thread
// (256K total instead of 2M; ~256 serialized ops per address).
__global__ __launch_bounds__(256)
void prep_Bt_kernel(const float* __restrict__ C) {
    __shared__ uint4 sm4[64][33];               // [oo][ii], padded
    const int i0 = (blockIdx.x >> 4) * 32;      // 32 i-blocks
    const int o0 = (blockIdx.x & 15) * 64;      // 16 o-blocks
    const int tid = threadIdx.x;
    const int oo0 = tid & 63;                   // constant oo for this thread

    float facc = 0.0f;
    // read phase: 2048 (ii,oo) pairs, 8 per thread, coalesced over oo
#pragma unroll
    for (int k = 0; k < 8; k++) {
        int ii = (tid >> 6) + k * 4;
        const float* src = C + (size_t)(i0 + ii) * (OUTDIM * DEG1)
                             + (size_t)(o0 + oo0) * DEG1;
        facc += src[0];
        __half2 h0 = __floats2half2_rn(src[1] * CSCALE, src[2] * CSCALE);
        __half2 h1 = __floats2half2_rn(src[3] * CSCALE, src[4] * CSCALE);
        __half2 h2 = __floats2half2_rn(src[5] * CSCALE, src[6] * CSCALE);
        __half2 h3 = __floats2half2_rn(src[7] * CSCALE, src[8] * CSCALE);
        uint4 pk;
        pk.x = *(uint32_t*)&h0; pk.y = *(uint32_t*)&h1;
        pk.z = *(uint32_t*)&h2; pk.w = *(uint32_t*)&h3;
        sm4[oo0][ii] = pk;
    }
    atomicAdd(&g_bias[o0 + oo0], facc);         // T_0 == 1 contribution
    __syncthreads();

    // write phase: warp w handles oo = w*8..w*8+7; lane = ii -> 512 B runs
    const int w = tid >> 5;
    const int l = tid & 31;
#pragma unroll
    for (int r = 0; r < 8; r++) {
        int oo = w * 8 + r;
        uint4* dst = (uint4*)(g_Bt + (size_t)(o0 + oo) * KD2 + (size_t)i0 * 8);
        dst[l] = sm4[oo][l];
    }
}

// ============================ main GEMM ================================
__global__ __launch_bounds__(NTH, 3)
void cheby_gemm_kernel(float* __restrict__ out) {
    extern __shared__ uint32_t sm[];
    uint32_t* const Abuf = sm + MBW;                 // 2 stages
    uint32_t* const Bbuf = sm + MBW + 2 * A_WORDS;   // 3 slots
    const uint32_t mb = smem_u32(sm);                // full[s]=mb+16s, empty[s]=mb+16s+8

    const int tid  = threadIdx.x;
    const int wid  = tid >> 5;
    const int lane = tid & 31;
    const int gid  = lane >> 2;
    const int tg   = lane & 3;
    const int warp_m = wid & 1;     // 2 warps along M (64 rows each)
    const int warp_n = wid >> 1;    // 2 warps along N (32 cols each)
    const int m0 = blockIdx.x * TM;
    const int n0 = blockIdx.y * TN;

    if (tid == 0) {
#pragma unroll
        for (int s2 = 0; s2 < 3; s2++) {
            MB_INIT(mb + s2 * 16, NTH);       // full (B cp.async complete)
            MB_INIT(mb + s2 * 16 + 8, NTH);   // empty
        }
    }
    __syncthreads();   // one-time init fence

    float acc[4][4][4];
#pragma unroll
    for (int mf = 0; mf < 4; mf++)
#pragma unroll
        for (int nf = 0; nf < 4; nf++)
#pragma unroll
            for (int q = 0; q < 4; q++) acc[mf][nf][q] = 0.0f;

    // B copier: 128 threads, thread -> (row tid&63, half tid>>6), 4 cp16 each
    const int brow = tid & 63;
    const int bhalf = tid >> 6;
    const __half* browsrc = g_Bt + (size_t)(n0 + brow) * KD2 + bhalf * 32;
    const uint32_t bdst_base = smem_u32(Bbuf) + (uint32_t)(brow * BSTW + bhalf * 16) * 4u;

    // ldmatrix per-lane base addresses
    const uint32_t a_ldm_base = smem_u32(Abuf)
        + (uint32_t)(warp_m * 64 + (lane & 7) + ((lane >> 3) & 1) * 8) * ROWB
        + (uint32_t)((lane >> 4) * 16);
    const uint32_t b_ldm_base = smem_u32(Bbuf)
        + (uint32_t)(warp_n * 32 + (lane & 7) + (lane >> 4) * 8) * ROWB
        + (uint32_t)(((lane >> 3) & 1) * 16);

    // ---- prologue: fill B slot0 (jj=0), slot1 (jj=1) ----
#pragma unroll
    for (int q = 0; q < 4; q++) cp_async16(bdst_base + q * 16, browsrc + q * 8);
    CP_MB_ARRIVE(mb + 0 * 16);
#pragma unroll
    for (int q = 0; q < 4; q++)
        cp_async16(bdst_base + B_BYTES + q * 16, browsrc + KC + q * 8);
    CP_MB_ARRIVE(mb + 1 * 16);

    // A producer: thread = row tid, full 64-wide K row (8 inputs x deg 1..8)
    const float4* tsrc = (const float4*)(g_t + (size_t)(m0 + tid) * INDIM);
    float4 t0 = tsrc[0], t1 = tsrc[1];     // inputs 0..7 for jj=0
    {
        uint32_t* dst = Abuf + tid * ASTW;
#pragma unroll
        for (int e = 0; e < 8; e++) {
            float t = (e < 4) ? (&t0.x)[e] : (&t1.x)[e - 4];
            float t2 = t + t;
            float v[8];
            v[0] = t;
            float u0 = 1.0f, u1 = t;
#pragma unroll
            for (int d = 2; d <= 8; d++) {
                float u2 = fmaf(t2, u1, -u0);
                v[d - 1] = u2;
                u0 = u1; u1 = u2;
            }
            __half2 h0 = __floats2half2_rn(v[0], v[1]);
            __half2 h1 = __floats2half2_rn(v[2], v[3]);
            __half2 h2 = __floats2half2_rn(v[4], v[5]);
            __half2 h3 = __floats2half2_rn(v[6], v[7]);
            uint4 pk;
            pk.x = *(uint32_t*)&h0; pk.y = *(uint32_t*)&h1;
            pk.z = *(uint32_t*)&h2; pk.w = *(uint32_t*)&h3;
            *(uint4*)(dst + e * 4) = pk;
        }
    }
    t0 = tsrc[2]; t1 = tsrc[3];            // t for producing A[1]
    __syncthreads();                       // A[0] visible

    // ---- prologue: preload (jj=0, kc=0) fragments ----
    uint32_t afr[2][4][4], bfr[2][2][4];
    int pb = 0;
    MB_WAIT(mb + 0 * 16, 0);               // full[0], phase 0
#pragma unroll
    for (int mf = 0; mf < 4; mf++)
        ldm4(afr[0][mf], a_ldm_base + (uint32_t)(mf * 16 * ROWB));
#pragma unroll
    for (int p = 0; p < 2; p++)
        ldm4(bfr[0][p], b_ldm_base + (uint32_t)(p * 16 * ROWB));

    int bb = 0;        // jj % 3
    int q3 = 0;        // jj / 3

#pragma unroll 1
    for (int jj = 0; jj < NITER; jj++) {
        const int s = jj & 1;
        const uint32_t a_addr0 = a_ldm_base + (uint32_t)(s * A_BYTES);
        const uint32_t b_addr0 = b_ldm_base + (uint32_t)(bb * B_BYTES);

        // ---- kc = 0..2: prefetch kc+1, MMA kc (tensor engaged at once) ----
#pragma unroll
        for (int kc = 0; kc < 3; kc++) {
            const uint32_t kb = (kc + 1) * 32;
            const int nx = pb ^ 1;
#pragma unroll
            for (int mf = 0; mf < 4; mf++)
                ldm4(afr[nx][mf], a_addr0 + (uint32_t)(mf * 16 * ROWB) + kb);
#pragma unroll
            for (int p = 0; p < 2; p++)
                ldm4(bfr[nx][p], b_addr0 + (uint32_t)(p * 16 * ROWB) + kb);
#pragma unroll
            for (int p = 0; p < 2; p++) {
#pragma unroll
                for (int mf = 0; mf < 4; mf++) {
                    mma16(acc[mf][2 * p],     afr[pb][mf], bfr[pb][p][0], bfr[pb][p][1]);
                    mma16(acc[mf][2 * p + 1], afr[pb][mf], bfr[pb][p][2], bfr[pb][p][3]);
                }
            }
            pb ^= 1;
        }

        // ---- boundary work (kc3 MMAs held back to cover it) ----
        // produce A[jj+1] into stage s^1 (FMA pipe; hides under kc drain)
        if (jj + 1 < NITER) {
            uint32_t* dst = Abuf + (s ^ 1) * A_WORDS + tid * ASTW;
#pragma unroll
            for (int e = 0; e < 8; e++) {
                float t = (e < 4) ? (&t0.x)[e] : (&t1.x)[e - 4];
                float t2 = t + t;
                float v[8];
                v[0] = t;
                float u0 = 1.0f, u1 = t;
#pragma unroll
                for (int d = 2; d <= 8; d++) {
                    float u2 = fmaf(t2, u1, -u0);
                    v[d - 1] = u2;
                    u0 = u1; u1 = u2;
                }
                __half2 h0 = __floats2half2_rn(v[0], v[1]);
                __half2 h1 = __floats2half2_rn(v[2], v[3]);
                __half2 h2 = __floats2half2_rn(v[4], v[5]);
                __half2 h3 = __floats2half2_rn(v[6], v[7]);
                uint4 pk;
                pk.x = *(uint32_t*)&h0; pk.y = *(uint32_t*)&h1;
                pk.z = *(uint32_t*)&h2; pk.w = *(uint32_t*)&h3;
                *(uint4*)(dst + e * 4) = pk;
            }
            if (jj + 2 < NITER) {
                t0 = tsrc[(jj + 2) * 2];
                t1 = tsrc[(jj + 2) * 2 + 1];
            }
        }

        // fill B[jj+2] into slot (bb+2)%3
        if (jj + 2 < NITER) {
            int bb2 = (bb >= 1) ? bb - 1 : 2;          // (bb+2)%3
            if (jj >= 1) {
                int pe = ((bb == 0) ? (q3 - 1) : q3) & 1;  // ((jj-1)/3)&1
                MB_WAIT(mb + bb2 * 16 + 8, pe);
            }
            const __half* src = browsrc + (jj + 2) * KC;
            uint32_t dst = bdst_base + (uint32_t)(bb2 * B_BYTES);
#pragma unroll
            for (int q = 0; q < 4; q++) cp_async16(dst + q * 16, src + q * 8);
            CP_MB_ARRIVE(mb + bb2 * 16);
        }

        // A[jj+1] visible; all A[s]/B[bb] ldm reads complete
        __syncthreads();
        MB_ARRIVE(mb + bb * 16 + 8);       // release B slot jj

        const int bbn = (bb == 2) ? 0 : bb + 1;
        const int q3n = (bb == 2) ? q3 + 1 : q3;

        // cross-jj prefetch: (jj+1, kc0) fragments before kc3 MMAs
        if (jj + 1 < NITER) {
            MB_WAIT(mb + bbn * 16, q3n & 1);
            const uint32_t a_n = a_ldm_base + (uint32_t)((s ^ 1) * A_BYTES);
            const uint32_t b_n = b_ldm_base + (uint32_t)(bbn * B_BYTES);
            const int nx = pb ^ 1;
#pragma unroll
            for (int mf = 0; mf < 4; mf++)
                ldm4(afr[nx][mf], a_n + (uint32_t)(mf * 16 * ROWB));
#pragma unroll
            for (int p = 0; p < 2; p++)
                ldm4(bfr[nx][p], b_n + (uint32_t)(p * 16 * ROWB));
        }

        // ---- kc3 MMAs: cover the boundary latency ----
#pragma unroll
        for (int p = 0; p < 2; p++) {
#pragma unroll
            for (int mf = 0; mf < 4; mf++) {
                mma16(acc[mf][2 * p],     afr[pb][mf], bfr[pb][p][0], bfr[pb][p][1]);
                mma16(acc[mf][2 * p + 1], afr[pb][mf], bfr[pb][p][2], bfr[pb][p][3]);
            }
        }
        pb ^= 1;

        bb = bbn; q3 = q3n;
    }

    // ---- epilogue: unscale, add T0 bias, write D ----
#pragma unroll
    for (int nf = 0; nf < 4; nf++) {
        int col = n0 + warp_n * 32 + nf * 8 + tg * 2;
        float2 bv = *(const float2*)&g_bias[col];
#pragma unroll
        for (int mf = 0; mf < 4; mf++) {
            int row = m0 + warp_m * 64 + mf * 16 + gid;
            float2* p0 = (float2*)(out + (size_t)row * OUTDIM + col);
            float2* p1 = (float2*)(out + (size_t)(row + 8) * OUTDIM + col);
            *p0 = make_float2(fmaf(acc[mf][nf][0], CINV, bv.x),
                              fmaf(acc[mf][nf][1], CINV, bv.y));
            *p1 = make_float2(fmaf(acc[mf][nf][2], CINV, bv.x),
                              fmaf(acc[mf][nf][3], CINV, bv.y));
        }
    }
}

// ============================ host launch ==============================
extern "C" void kernel_launch(void* const* d_in, const int* in_sizes, int n_in,
                              void* d_out, int out_size) {
    const float* x;
    const float* C;
    if (in_sizes[0] == BATCH * INDIM) { x = (const float*)d_in[0]; C = (const float*)d_in[1]; }
    else                              { x = (const float*)d_in[1]; C = (const float*)d_in[0]; }
    float* out = (float*)d_out;

    prep_t_kernel<<<(BATCH * INDIM) / (256 * 4), 256>>>(x);
    prep_Bt_kernel<<<512, 256>>>(C);

    static int smem_set = 0;
    if (!smem_set) {
        cudaFuncSetAttribute(cheby_gemm_kernel,
                             cudaFuncAttributeMaxDynamicSharedMemorySize, SMEM_BYTES);
        smem_set = 1;
    }
    dim3 grid(BATCH / TM, OUTDIM / TN, 1);   // 64 x 16 = 1024 CTAs, 3/SM
    cheby_gemm_kernel<<<grid, NTH, SMEM_BYTES>>>(out);
}

// round 17
// speedup vs baseline: 1.4726x; 1.0124x over previous
#include <cuda_runtime.h>
#include <cuda_fp16.h>
#include <cstdint>

// ============================ problem sizes ============================
#define BATCH   8192
#define INDIM   1024
#define OUTDIM  1024
#define DEG1    9
#define KD2     (INDIM * 8)         // 8192 GEMM K (d=1..8; d=0 folded into bias)
#define TM      128
#define TN      64                  // finer N-tiles: 1024 CTAs -> 1.2% imbalance
#define KC      64                  // 8 inputs x 8 degrees per stage
#define NITER   (KD2 / KC)          // 128
#define NTH     128                 // 4 warps, warp tile 64x32

#define ASTW    36                  // A row stride in 32-bit words
#define BSTW    36
#define ROWB    144                 // row stride in bytes
#define A_WORDS (TM * ASTW)         // 4608 words = 18432 B per stage
#define B_WORDS (TN * BSTW)         // 2304 words = 9216 B per slot
#define A_BYTES (A_WORDS * 4)
#define B_BYTES (B_WORDS * 4)
#define MBW     16                  // 64 B header for 6 mbarriers
#define SMEM_BYTES ((MBW + 2 * A_WORDS + 3 * B_WORDS) * 4)   // 64576 -> 3 CTAs/SM

#define CSCALE   64.0f
#define CINV     (1.0f / 64.0f)

// __device__ scratch (static: allocation-guard safe)
__device__ __half g_Bt[(size_t)OUTDIM * KD2];   // Bt[o][i*8+d-1] * 64, fp16
__device__ float  g_bias[OUTDIM];               // sum_i C[i][o][0]

// ============================ helpers ==================================
__device__ __forceinline__ void cp_async16(uint32_t smem_dst, const void* gsrc) {
    asm volatile("cp.async.cg.shared.global [%0], [%1], 16;"
                 :: "r"(smem_dst), "l"(gsrc) : "memory");
}
__device__ __forceinline__ uint32_t smem_u32(const void* p) {
    uint32_t a;
    asm("{ .reg .u64 t; cvta.to.shared.u64 t, %1; cvt.u32.u64 %0, t; }" : "=r"(a) : "l"(p));
    return a;
}
// fast tanh (sm_75+ MUFU.TANH, rel err <= 2^-11) + clip
__device__ __forceinline__ float tanh_clip(float v) {
    float r;
    asm("tanh.approx.f32 %0, %1;" : "=f"(r) : "f"(v));
    return fminf(fmaxf(r, -0.999f), 0.999f);
}
#define MB_INIT(addr, cnt) \
    asm volatile("mbarrier.init.shared.b64 [%0], %1;" :: "r"(addr), "r"(cnt) : "memory")
#define MB_ARRIVE(addr) \
    asm volatile("{ .reg .b64 t; mbarrier.arrive.shared.b64 t, [%0]; }" :: "r"(addr) : "memory")
#define CP_MB_ARRIVE(addr) \
    asm volatile("cp.async.mbarrier.arrive.noinc.shared.b64 [%0];" :: "r"(addr) : "memory")
#define MB_WAIT(addr, parity) do {                                                       \
    uint32_t _mbar = (uint32_t)(addr);                                                   \
    uint32_t _par  = (uint32_t)(parity);                                                 \
    uint32_t _done;                                                                      \
    asm volatile("{\n\t.reg .pred p;\n\t"                                                \
        "mbarrier.try_wait.parity.acquire.cta.shared::cta.b64 p, [%1], %2;\n\t"          \
        "selp.b32 %0, 1, 0, p;\n\t}"                                                     \
        : "=r"(_done) : "r"(_mbar), "r"(_par) : "memory");                               \
    if (!_done) {                                                                        \
        asm volatile("{\n\t.reg .pred P1;\n\t"                                           \
            "WL_%=:\n\t"                                                                 \
            "mbarrier.try_wait.parity.acquire.cta.shared::cta.b64 P1, [%0], %1, 0x989680;\n\t" \
            "@P1 bra.uni WD_%=;\n\t"                                                     \
            "bra.uni WL_%=;\n\t"                                                         \
            "WD_%=:\n\t}"                                                                \
            :: "r"(_mbar), "r"(_par) : "memory");                                        \
    }                                                                                    \
} while (0)

// mma m16n8k16 row.col f32.f16.f16.f32 — NON-volatile (pure register op)
__device__ __forceinline__ void mma16(float* c, const uint32_t* a, uint32_t b0, uint32_t b1) {
    asm("mma.sync.aligned.m16n8k16.row.col.f32.f16.f16.f32 "
        "{%0,%1,%2,%3}, {%4,%5,%6,%7}, {%8,%9}, {%0,%1,%2,%3};"
        : "+f"(c[0]), "+f"(c[1]), "+f"(c[2]), "+f"(c[3])
        : "r"(a[0]), "r"(a[1]), "r"(a[2]), "r"(a[3]), "r"(b0), "r"(b1));
}
__device__ __forceinline__ void ldm4(uint32_t* r, uint32_t addr) {
    asm volatile("ldmatrix.sync.aligned.m8n8.x4.shared.b16 {%0,%1,%2,%3}, [%4];"
                 : "=r"(r[0]), "=r"(r[1]), "=r"(r[2]), "=r"(r[3]) : "r"(addr));
}

// Chebyshev basis from raw x chunk (tanh fused): 8 inputs -> 64 fp16
__device__ __forceinline__ void produce_chunk(uint32_t* dst, const float4& x0, const float4& x1) {
#pragma unroll
    for (int e = 0; e < 8; e++) {
        float t = tanh_clip((e < 4) ? (&x0.x)[e] : (&x1.x)[e - 4]);
        float t2 = t + t;
        float v[8];
        v[0] = t;
        float u0 = 1.0f, u1 = t;
#pragma unroll
        for (int d = 2; d <= 8; d++) {
            float u2 = fmaf(t2, u1, -u0);
            v[d - 1] = u2;
            u0 = u1; u1 = u2;
        }
        __half2 h0 = __floats2half2_rn(v[0], v[1]);
        __half2 h1 = __floats2half2_rn(v[2], v[3]);
        __half2 h2 = __floats2half2_rn(v[4], v[5]);
        __half2 h3 = __floats2half2_rn(v[6], v[7]);
        uint4 pk;
        pk.x = *(uint32_t*)&h0; pk.y = *(uint32_t*)&h1;
        pk.z = *(uint32_t*)&h2; pk.w = *(uint32_t*)&h3;
        *(uint4*)(dst + e * 4) = pk;
    }
}

// ============ prep 0: zero g_bias (before prep_Bt atomics) =============
__global__ __launch_bounds__(256)
void zero_bias_kernel() {
    ((float4*)g_bias)[threadIdx.x] = make_float4(0.f, 0.f, 0.f, 0.f);
}

// ==== prep: C[i,o,d>=1]*64 -> Bt[o, i*8+d-1]; d=0 -> bias ==============
// smem-transposed: reads coalesced over o, writes coalesced over i.
// oo = tid & 63 constant per thread -> ONE atomicAdd per thread.
__global__ __launch_bounds__(256)
void prep_Bt_kernel(const float* __restrict__ C) {
    __shared__ uint4 sm4[64][33];               // [oo][ii], padded
    const int i0 = (blockIdx.x >> 4) * 32;      // 32 i-blocks
    const int o0 = (blockIdx.x & 15) * 64;      // 16 o-blocks
    const int tid = threadIdx.x;
    const int oo0 = tid & 63;                   // constant oo for this thread

    float facc = 0.0f;
#pragma unroll
    for (int k = 0; k < 8; k++) {
        int ii = (tid >> 6) + k * 4;
        const float* src = C + (size_t)(i0 + ii) * (OUTDIM * DEG1)
                             + (size_t)(o0 + oo0) * DEG1;
        facc += src[0];
        __half2 h0 = __floats2half2_rn(src[1] * CSCALE, src[2] * CSCALE);
        __half2 h1 = __floats2half2_rn(src[3] * CSCALE, src[4] * CSCALE);
        __half2 h2 = __floats2half2_rn(src[5] * CSCALE, src[6] * CSCALE);
        __half2 h3 = __floats2half2_rn(src[7] * CSCALE, src[8] * CSCALE);
        uint4 pk;
        pk.x = *(uint32_t*)&h0; pk.y = *(uint32_t*)&h1;
        pk.z = *(uint32_t*)&h2; pk.w = *(uint32_t*)&h3;
        sm4[oo0][ii] = pk;
    }
    atomicAdd(&g_bias[o0 + oo0], facc);         // T_0 == 1 contribution
    __syncthreads();

    const int w = tid >> 5;
    const int l = tid & 31;
#pragma unroll
    for (int r = 0; r < 8; r++) {
        int oo = w * 8 + r;
        uint4* dst = (uint4*)(g_Bt + (size_t)(o0 + oo) * KD2 + (size_t)i0 * 8);
        dst[l] = sm4[oo][l];
    }
}

// ============================ main GEMM ================================
__global__ __launch_bounds__(NTH, 3)
void cheby_gemm_kernel(const float* __restrict__ x, float* __restrict__ out) {
    extern __shared__ uint32_t sm[];
    uint32_t* const Abuf = sm + MBW;                 // 2 stages
    uint32_t* const Bbuf = sm + MBW + 2 * A_WORDS;   // 3 slots
    const uint32_t mb = smem_u32(sm);                // full[s]=mb+16s, empty[s]=mb+16s+8

    const int tid  = threadIdx.x;
    const int wid  = tid >> 5;
    const int lane = tid & 31;
    const int gid  = lane >> 2;
    const int tg   = lane & 3;
    const int warp_m = wid & 1;     // 2 warps along M (64 rows each)
    const int warp_n = wid >> 1;    // 2 warps along N (32 cols each)
    const int m0 = blockIdx.x * TM;
    const int n0 = blockIdx.y * TN;

    if (tid == 0) {
#pragma unroll
        for (int s2 = 0; s2 < 3; s2++) {
            MB_INIT(mb + s2 * 16, NTH);       // full (B cp.async complete)
            MB_INIT(mb + s2 * 16 + 8, NTH);   // empty
        }
    }
    __syncthreads();   // one-time init fence

    float acc[4][4][4];
#pragma unroll
    for (int mf = 0; mf < 4; mf++)
#pragma unroll
        for (int nf = 0; nf < 4; nf++)
#pragma unroll
            for (int q = 0; q < 4; q++) acc[mf][nf][q] = 0.0f;

    // B copier: 128 threads, thread -> (row tid&63, half tid>>6), 4 cp16 each
    const int brow = tid & 63;
    const int bhalf = tid >> 6;
    const __half* browsrc = g_Bt + (size_t)(n0 + brow) * KD2 + bhalf * 32;
    const uint32_t bdst_base = smem_u32(Bbuf) + (uint32_t)(brow * BSTW + bhalf * 16) * 4u;

    // ldmatrix per-lane base addresses
    const uint32_t a_ldm_base = smem_u32(Abuf)
        + (uint32_t)(warp_m * 64 + (lane & 7) + ((lane >> 3) & 1) * 8) * ROWB
        + (uint32_t)((lane >> 4) * 16);
    const uint32_t b_ldm_base = smem_u32(Bbuf)
        + (uint32_t)(warp_n * 32 + (lane & 7) + (lane >> 4) * 8) * ROWB
        + (uint32_t)(((lane >> 3) & 1) * 16);

    // ---- prologue: fill B slot0 (jj=0), slot1 (jj=1) ----
#pragma unroll
    for (int q = 0; q < 4; q++) cp_async16(bdst_base + q * 16, browsrc + q * 8);
    CP_MB_ARRIVE(mb + 0 * 16);
#pragma unroll
    for (int q = 0; q < 4; q++)
        cp_async16(bdst_base + B_BYTES + q * 16, browsrc + KC + q * 8);
    CP_MB_ARRIVE(mb + 1 * 16);

    // A producer: thread = row tid; reads RAW x, tanh fused (MUFU)
    const float4* tsrc = (const float4*)(x + (size_t)(m0 + tid) * INDIM);
    float4 t0 = tsrc[0], t1 = tsrc[1];     // raw x, inputs 0..7 for jj=0
    produce_chunk(Abuf + tid * ASTW, t0, t1);
    t0 = tsrc[2]; t1 = tsrc[3];            // raw x for producing A[1]
    __syncthreads();                       // A[0] visible

    // ---- prologue: preload (jj=0, kc=0) fragments ----
    uint32_t afr[2][4][4], bfr[2][2][4];
    int pb = 0;
    MB_WAIT(mb + 0 * 16, 0);               // full[0], phase 0
#pragma unroll
    for (int mf = 0; mf < 4; mf++)
        ldm4(afr[0][mf], a_ldm_base + (uint32_t)(mf * 16 * ROWB));
#pragma unroll
    for (int p = 0; p < 2; p++)
        ldm4(bfr[0][p], b_ldm_base + (uint32_t)(p * 16 * ROWB));

    int bb = 0;        // jj % 3
    int q3 = 0;        // jj / 3

#pragma unroll 1
    for (int jj = 0; jj < NITER; jj++) {
        const int s = jj & 1;
        const uint32_t a_addr0 = a_ldm_base + (uint32_t)(s * A_BYTES);
        const uint32_t b_addr0 = b_ldm_base + (uint32_t)(bb * B_BYTES);

        // ---- kc = 0..2: prefetch kc+1, MMA kc (tensor engaged at once) ----
#pragma unroll
        for (int kc = 0; kc < 3; kc++) {
            const uint32_t kb = (kc + 1) * 32;
            const int nx = pb ^ 1;
#pragma unroll
            for (int mf = 0; mf < 4; mf++)
                ldm4(afr[nx][mf], a_addr0 + (uint32_t)(mf * 16 * ROWB) + kb);
#pragma unroll
            for (int p = 0; p < 2; p++)
                ldm4(bfr[nx][p], b_addr0 + (uint32_t)(p * 16 * ROWB) + kb);
#pragma unroll
            for (int p = 0; p < 2; p++) {
#pragma unroll
                for (int mf = 0; mf < 4; mf++) {
                    mma16(acc[mf][2 * p],     afr[pb][mf], bfr[pb][p][0], bfr[pb][p][1]);
                    mma16(acc[mf][2 * p + 1], afr[pb][mf], bfr[pb][p][2], bfr[pb][p][3]);
                }
            }
            pb ^= 1;
        }

        // ---- boundary work (kc3 MMAs held back to cover it) ----
        // produce A[jj+1] into stage s^1 (MUFU+FMA; hides under kc drain)
        if (jj + 1 < NITER) {
            produce_chunk(Abuf + (s ^ 1) * A_WORDS + tid * ASTW, t0, t1);
            if (jj + 2 < NITER) {
                t0 = tsrc[(jj + 2) * 2];
                t1 = tsrc[(jj + 2) * 2 + 1];
            }
        }

        // fill B[jj+2] into slot (bb+2)%3
        if (jj + 2 < NITER) {
            int bb2 = (bb >= 1) ? bb - 1 : 2;          // (bb+2)%3
            if (jj >= 1) {
                int pe = ((bb == 0) ? (q3 - 1) : q3) & 1;  // ((jj-1)/3)&1
                MB_WAIT(mb + bb2 * 16 + 8, pe);
            }
            const __half* src = browsrc + (jj + 2) * KC;
            uint32_t dst = bdst_base + (uint32_t)(bb2 * B_BYTES);
#pragma unroll
            for (int q = 0; q < 4; q++) cp_async16(dst + q * 16, src + q * 8);
            CP_MB_ARRIVE(mb + bb2 * 16);
        }

        // A[jj+1] visible; all A[s]/B[bb] ldm reads complete
        __syncthreads();
        MB_ARRIVE(mb + bb * 16 + 8);       // release B slot jj

        const int bbn = (bb == 2) ? 0 : bb + 1;
        const int q3n = (bb == 2) ? q3 + 1 : q3;

        // cross-jj prefetch: (jj+1, kc0) fragments before kc3 MMAs
        if (jj + 1 < NITER) {
            MB_WAIT(mb + bbn * 16, q3n & 1);
            const uint32_t a_n = a_ldm_base + (uint32_t)((s ^ 1) * A_BYTES);
            const uint32_t b_n = b_ldm_base + (uint32_t)(bbn * B_BYTES);
            const int nx = pb ^ 1;
#pragma unroll
            for (int mf = 0; mf < 4; mf++)
                ldm4(afr[nx][mf], a_n + (uint32_t)(mf * 16 * ROWB));
#pragma unroll
            for (int p = 0; p < 2; p++)
                ldm4(bfr[nx][p], b_n + (uint32_t)(p * 16 * ROWB));
        }

        // ---- kc3 MMAs: cover the boundary latency ----
#pragma unroll
        for (int p = 0; p < 2; p++) {
#pragma unroll
            for (int mf = 0; mf < 4; mf++) {
                mma16(acc[mf][2 * p],     afr[pb][mf], bfr[pb][p][0], bfr[pb][p][1]);
                mma16(acc[mf][2 * p + 1], afr[pb][mf], bfr[pb][p][2], bfr[pb][p][3]);
            }
        }
        pb ^= 1;

        bb = bbn; q3 = q3n;
    }

    // ---- epilogue: unscale, add T0 bias, write D ----
#pragma unroll
    for (int nf = 0; nf < 4; nf++) {
        int col = n0 + warp_n * 32 + nf * 8 + tg * 2;
        float2 bv = *(const float2*)&g_bias[col];
#pragma unroll
        for (int mf = 0; mf < 4; mf++) {
            int row = m0 + warp_m * 64 + mf * 16 + gid;
            float2* p0 = (float2*)(out + (size_t)row * OUTDIM + col);
            float2* p1 = (float2*)(out + (size_t)(row + 8) * OUTDIM + col);
            *p0 = make_float2(fmaf(acc[mf][nf][0], CINV, bv.x),
                              fmaf(acc[mf][nf][1], CINV, bv.y));
            *p1 = make_float2(fmaf(acc[mf][nf][2], CINV, bv.x),
                              fmaf(acc[mf][nf][3], CINV, bv.y));
        }
    }
}

// ============================ host launch ==============================
extern "C" void kernel_launch(void* const* d_in, const int* in_sizes, int n_in,
                              void* d_out, int out_size) {
    const float* x;
    const float* C;
    if (in_sizes[0] == BATCH * INDIM) { x = (const float*)d_in[0]; C = (const float*)d_in[1]; }
    else                              { x = (const float*)d_in[1]; C = (const float*)d_in[0]; }
    float* out = (float*)d_out;

    zero_bias_kernel<<<1, 256>>>();
    prep_Bt_kernel<<<512, 256>>>(C);

    static int smem_set = 0;
    if (!smem_set) {
        cudaFuncSetAttribute(cheby_gemm_kernel,
                             cudaFuncAttributeMaxDynamicSharedMemorySize, SMEM_BYTES);
        smem_set = 1;
    }
    dim3 grid(BATCH / TM, OUTDIM / TN, 1);   // 64 x 16 = 1024 CTAs, 3/SM
    cheby_gemm_kernel<<<grid, NTH, SMEM_BYTES>>>(x, out);
}